// round 5
// baseline (speedup 1.0000x reference)
#include <cuda_runtime.h>

#define T_STEPS 8192
#define DH 2048
#define RNN_CTAS 128
#define SENT 0xFFC00001u

typedef unsigned long long ull;

__device__ __align__(16) float g_pre[(size_t)T_STEPS * DH];
__device__ __align__(16) float g_H[(size_t)T_STEPS * DH];

__device__ __forceinline__ ull pack2(float a, float b) {
    ull r; asm("mov.b64 %0, {%1, %2};" : "=l"(r) : "f"(a), "f"(b)); return r;
}
__device__ __forceinline__ void unpack2(ull v, float& a, float& b) {
    asm("mov.b64 {%0, %1}, %2;" : "=f"(a), "=f"(b) : "l"(v));
}
__device__ __forceinline__ ull fma2(ull a, ull b, ull c) {
    ull d; asm("fma.rn.f32x2 %0, %1, %2, %3;" : "=l"(d) : "l"(a), "l"(b), "l"(c));
    return d;
}
__device__ __forceinline__ uint4 ld_rlx4(const uint4* p) {
    uint4 v;
    asm volatile("ld.relaxed.gpu.global.v4.u32 {%0,%1,%2,%3}, [%4];"
        : "=r"(v.x), "=r"(v.y), "=r"(v.z), "=r"(v.w) : "l"(p) : "memory");
    return v;
}
__device__ __forceinline__ void st_rlx(float* p, float v) {
    asm volatile("st.relaxed.gpu.global.f32 [%0], %1;" :: "l"(p), "f"(v) : "memory");
}
__device__ __forceinline__ bool has_sent(uint4 v) {
    return (v.x == SENT) | (v.y == SENT) | (v.z == SENT) | (v.w == SENT);
}

__global__ void init_kernel(const float* __restrict__ features,
                            const float* __restrict__ caption,
                            float* __restrict__ out) {
    int i = blockIdx.x * blockDim.x + threadIdx.x;
    if (i < DH) { g_H[i] = features[i]; out[i] = caption[i]; }
}

// poison H rows 1..T-1 with the sentinel
__global__ void poison_kernel() {
    uint4 s = make_uint4(SENT, SENT, SENT, SENT);
    uint4* p = reinterpret_cast<uint4*>(g_H + DH);
    const size_t n = (size_t)(T_STEPS - 1) * DH / 4;
    const size_t stride = (size_t)gridDim.x * blockDim.x;
    for (size_t k = (size_t)blockIdx.x * blockDim.x + threadIdx.x; k < n; k += stride)
        p[k] = s;
}

// C[m,n] = sum_k A[m*lda+k]*B[n*ldb+k] + bias[n], optional sigmoid.
template <int SIG>
__global__ void __launch_bounds__(256, 2)
sgemm_nt(const float* __restrict__ A, int lda,
         const float* __restrict__ B, int ldb,
         const float* __restrict__ bias,
         float* __restrict__ C, int ldc, int M, int K) {
    __shared__ __align__(16) ull   As[2][8][128];
    __shared__ __align__(16) float Bs[2][8][128];
    const int tid = threadIdx.x;
    const int tx = tid & 15, ty = tid >> 4;
    const int bm = blockIdx.y << 7, bn = blockIdx.x << 7;
    const int lr = tid >> 1, lc = (tid & 1) << 2;
    const float* Ap = A + (size_t)(bm + lr) * lda + lc;
    const float* Bp = B + (size_t)(bn + lr) * ldb + lc;
    const bool av = (bm + lr) < M;

    ull acc[8][4];
#pragma unroll
    for (int i = 0; i < 8; ++i)
#pragma unroll
        for (int j = 0; j < 4; ++j) acc[i][j] = 0ULL;

    float4 af = av ? *reinterpret_cast<const float4*>(Ap) : make_float4(0,0,0,0);
    float4 bf = *reinterpret_cast<const float4*>(Bp);
    As[0][lc+0][lr] = pack2(af.x, af.x); As[0][lc+1][lr] = pack2(af.y, af.y);
    As[0][lc+2][lr] = pack2(af.z, af.z); As[0][lc+3][lr] = pack2(af.w, af.w);
    Bs[0][lc+0][lr] = bf.x; Bs[0][lc+1][lr] = bf.y;
    Bs[0][lc+2][lr] = bf.z; Bs[0][lc+3][lr] = bf.w;
    __syncthreads();

    const int nIter = K >> 3;
    int buf = 0;
    for (int kt = 0; kt < nIter; ++kt) {
        const bool nxt = (kt + 1) < nIter;
        if (nxt) {
            af = av ? *reinterpret_cast<const float4*>(Ap + ((kt+1) << 3)) : make_float4(0,0,0,0);
            bf = *reinterpret_cast<const float4*>(Bp + ((kt+1) << 3));
        }
#pragma unroll
        for (int k = 0; k < 8; ++k) {
            const ulonglong2* ap2 = reinterpret_cast<const ulonglong2*>(&As[buf][k][ty << 3]);
            ulonglong2 a01 = ap2[0], a23 = ap2[1], a45 = ap2[2], a67 = ap2[3];
            const float4* bp4 = reinterpret_cast<const float4*>(&Bs[buf][k][tx << 3]);
            float4 b0 = bp4[0], b1 = bp4[1];
            ull ra[8] = {a01.x, a01.y, a23.x, a23.y, a45.x, a45.y, a67.x, a67.y};
            ull rb[4] = {pack2(b0.x, b0.y), pack2(b0.z, b0.w),
                         pack2(b1.x, b1.y), pack2(b1.z, b1.w)};
#pragma unroll
            for (int i = 0; i < 8; ++i)
#pragma unroll
                for (int j = 0; j < 4; ++j) acc[i][j] = fma2(ra[i], rb[j], acc[i][j]);
        }
        if (nxt) {
            const int nb = buf ^ 1;
            As[nb][lc+0][lr] = pack2(af.x, af.x); As[nb][lc+1][lr] = pack2(af.y, af.y);
            As[nb][lc+2][lr] = pack2(af.z, af.z); As[nb][lc+3][lr] = pack2(af.w, af.w);
            Bs[nb][lc+0][lr] = bf.x; Bs[nb][lc+1][lr] = bf.y;
            Bs[nb][lc+2][lr] = bf.z; Bs[nb][lc+3][lr] = bf.w;
        }
        __syncthreads();
        buf ^= 1;
    }

    const float4* bias4 = reinterpret_cast<const float4*>(bias + bn + (tx << 3));
    float4 bv0 = bias4[0], bv1 = bias4[1];
    float bb[8] = {bv0.x, bv0.y, bv0.z, bv0.w, bv1.x, bv1.y, bv1.z, bv1.w};
#pragma unroll
    for (int i = 0; i < 8; ++i) {
        int cm = bm + (ty << 3) + i;
        if (cm < M) {
            float o[8];
#pragma unroll
            for (int j = 0; j < 4; ++j) unpack2(acc[i][j], o[2*j], o[2*j+1]);
#pragma unroll
            for (int j = 0; j < 8; ++j) {
                float v = o[j] + bb[j];
                if (SIG) v = 1.0f / (1.0f + __expf(-v));
                o[j] = v;
            }
            float4* cp = reinterpret_cast<float4*>(C + (size_t)cm * ldc + bn + (tx << 3));
            cp[0] = make_float4(o[0], o[1], o[2], o[3]);
            cp[1] = make_float4(o[4], o[5], o[6], o[7]);
        }
    }
}

// Persistent recurrence v2: 128 CTAs x 512 thr, W_hh register-resident.
// One row per warp (16 rows/CTA), intra-warp reduction only, ONE barrier
// per step, sentinel data-polling (512 pollers x 16B).
__global__ void __launch_bounds__(512, 1)
rnn_kernel(const float* __restrict__ Wh) {
    const int tid = threadIdx.x;
    const int warp = tid >> 5, lane = tid & 31;
    const int row = (blockIdx.x << 4) + warp;

    // weights for this warp's row: cols j*128 + lane*4 (+0..3), j=0..15
    ull wreg[32];
    {
        const float* wp = Wh + (size_t)row * (2 * DH) + DH + (lane << 2);
#pragma unroll
        for (int j = 0; j < 16; ++j) {
            float4 v = *reinterpret_cast<const float4*>(wp + (j << 7));
            wreg[2*j]   = pack2(v.x, v.y);
            wreg[2*j+1] = pack2(v.z, v.w);
        }
    }

    __shared__ __align__(16) float hs[2][DH];   // parity double-buffered

    for (int t = 1; t < T_STEPS; ++t) {
        const int pb = t & 1;

        // poll my 16B of h_{t-1} straight from L2 until non-sentinel
        const uint4* hp = reinterpret_cast<const uint4*>(
            &g_H[(size_t)(t - 1) * DH]) + tid;
        uint4 v;
        do { v = ld_rlx4(hp); } while (has_sent(v));
        *reinterpret_cast<uint4*>(&hs[pb][tid << 2]) = v;

        float prev = 0.f;
        if (lane == 0) prev = g_pre[(size_t)t * DH + row];

        __syncthreads();  // sole barrier per step

        ull acc0 = 0ULL, acc1 = 0ULL;
#pragma unroll
        for (int j = 0; j < 16; ++j) {
            float4 hv = *reinterpret_cast<const float4*>(
                &hs[pb][(j << 7) + (lane << 2)]);
            acc0 = fma2(wreg[2*j],   pack2(hv.x, hv.y), acc0);
            acc1 = fma2(wreg[2*j+1], pack2(hv.z, hv.w), acc1);
        }
        float a, b, c, d;
        unpack2(acc0, a, b); unpack2(acc1, c, d);
        float s = (a + b) + (c + d);
#pragma unroll
        for (int o = 16; o > 0; o >>= 1) s += __shfl_xor_sync(0xffffffffu, s, o);
        if (lane == 0) {
            float x = s + prev;
            st_rlx(&g_H[(size_t)t * DH + row], 1.0f / (1.0f + __expf(-x)));
        }
        // no second barrier: hs is parity-buffered; a warp can only reach
        // the step t+2 write after the t+1 barrier, which every warp only
        // passes after its step-t read of hs[pb].
    }
}

extern "C" void kernel_launch(void* const* d_in, const int* in_sizes, int n_in,
                              void* d_out, int out_size) {
    (void)in_sizes; (void)n_in; (void)out_size;
    const float* features = (const float*)d_in[0];
    const float* caption  = (const float*)d_in[1];
    const float* W_h      = (const float*)d_in[2];
    const float* b_h      = (const float*)d_in[3];
    const float* W_o      = (const float*)d_in[4];
    const float* b_o      = (const float*)d_in[5];
    float* out = (float*)d_out;

    void *preV = nullptr, *hV = nullptr;
    cudaGetSymbolAddress(&preV, g_pre);
    cudaGetSymbolAddress(&hV, g_H);
    float* pre = (float*)preV;
    float* H   = (float*)hV;

    init_kernel<<<8, 256>>>(features, caption, out);
    poison_kernel<<<1024, 256>>>();

    dim3 grid(DH / 128, (T_STEPS - 1 + 127) / 128);  // 16 x 64
    sgemm_nt<0><<<grid, 256>>>(caption, DH, W_h, 2 * DH, b_h,
                               pre + DH, DH, T_STEPS - 1, DH);
    rnn_kernel<<<RNN_CTAS, 512>>>(W_h);
    sgemm_nt<1><<<grid, 256>>>(H + DH, DH, W_o, DH, b_o,
                               out + DH, DH, T_STEPS - 1, DH);
}

// round 7
// speedup vs baseline: 1.5212x; 1.5212x over previous
#include <cuda_runtime.h>

#define T_STEPS 8192
#define DH 2048
#define RNN_CTAS 128

typedef unsigned long long ull;

__device__ __align__(16) float g_pre[(size_t)T_STEPS * DH];
__device__ __align__(16) float g_H[(size_t)T_STEPS * DH];
// tag-carrying sync words: (step<<32)|float_bits(h). 32KB, stays L2-hot.
__device__ __align__(16) ull g_sync[2][DH];

__device__ __forceinline__ ull pack2(float a, float b) {
    ull r; asm("mov.b64 %0, {%1, %2};" : "=l"(r) : "f"(a), "f"(b)); return r;
}
__device__ __forceinline__ void unpack2(ull v, float& a, float& b) {
    asm("mov.b64 {%0, %1}, %2;" : "=f"(a), "=f"(b) : "l"(v));
}
__device__ __forceinline__ ull fma2(ull a, ull b, ull c) {
    ull d; asm("fma.rn.f32x2 %0, %1, %2, %3;" : "=l"(d) : "l"(a), "l"(b), "l"(c));
    return d;
}
__device__ __forceinline__ void ld_rlx_2u64(const ull* p, ull& x, ull& y) {
    asm volatile("ld.relaxed.gpu.global.v2.u64 {%0,%1}, [%2];"
        : "=l"(x), "=l"(y) : "l"(p) : "memory");
}
__device__ __forceinline__ void st_rlx_u64(ull* p, ull v) {
    asm volatile("st.relaxed.gpu.global.u64 [%0], %1;" :: "l"(p), "l"(v) : "memory");
}

__global__ void init_kernel(const float* __restrict__ features,
                            const float* __restrict__ caption,
                            float* __restrict__ out) {
    int i = blockIdx.x * blockDim.x + threadIdx.x;
    if (i < DH) {
        g_sync[0][i] = (ull)__float_as_uint(features[i]);  // tag 0 = h_0
        g_sync[1][i] = 0xFFFFFFFF00000000ull;              // never-matching tag
        out[i] = caption[i];
    }
}

// C[m,n] = sum_k A[m*lda+k]*B[n*ldb+k] + bias[n], optional sigmoid.
template <int SIG>
__global__ void __launch_bounds__(256, 2)
sgemm_nt(const float* __restrict__ A, int lda,
         const float* __restrict__ B, int ldb,
         const float* __restrict__ bias,
         float* __restrict__ C, int ldc, int M, int K) {
    __shared__ __align__(16) ull   As[2][8][128];
    __shared__ __align__(16) float Bs[2][8][128];
    const int tid = threadIdx.x;
    const int tx = tid & 15, ty = tid >> 4;
    const int bm = blockIdx.y << 7, bn = blockIdx.x << 7;
    const int lr = tid >> 1, lc = (tid & 1) << 2;
    const float* Ap = A + (size_t)(bm + lr) * lda + lc;
    const float* Bp = B + (size_t)(bn + lr) * ldb + lc;
    const bool av = (bm + lr) < M;

    ull acc[8][4];
#pragma unroll
    for (int i = 0; i < 8; ++i)
#pragma unroll
        for (int j = 0; j < 4; ++j) acc[i][j] = 0ULL;

    float4 af = av ? *reinterpret_cast<const float4*>(Ap) : make_float4(0,0,0,0);
    float4 bf = *reinterpret_cast<const float4*>(Bp);
    As[0][lc+0][lr] = pack2(af.x, af.x); As[0][lc+1][lr] = pack2(af.y, af.y);
    As[0][lc+2][lr] = pack2(af.z, af.z); As[0][lc+3][lr] = pack2(af.w, af.w);
    Bs[0][lc+0][lr] = bf.x; Bs[0][lc+1][lr] = bf.y;
    Bs[0][lc+2][lr] = bf.z; Bs[0][lc+3][lr] = bf.w;
    __syncthreads();

    const int nIter = K >> 3;
    int buf = 0;
    for (int kt = 0; kt < nIter; ++kt) {
        const bool nxt = (kt + 1) < nIter;
        if (nxt) {
            af = av ? *reinterpret_cast<const float4*>(Ap + ((kt+1) << 3)) : make_float4(0,0,0,0);
            bf = *reinterpret_cast<const float4*>(Bp + ((kt+1) << 3));
        }
#pragma unroll
        for (int k = 0; k < 8; ++k) {
            const ulonglong2* ap2 = reinterpret_cast<const ulonglong2*>(&As[buf][k][ty << 3]);
            ulonglong2 a01 = ap2[0], a23 = ap2[1], a45 = ap2[2], a67 = ap2[3];
            const float4* bp4 = reinterpret_cast<const float4*>(&Bs[buf][k][tx << 3]);
            float4 b0 = bp4[0], b1 = bp4[1];
            ull ra[8] = {a01.x, a01.y, a23.x, a23.y, a45.x, a45.y, a67.x, a67.y};
            ull rb[4] = {pack2(b0.x, b0.y), pack2(b0.z, b0.w),
                         pack2(b1.x, b1.y), pack2(b1.z, b1.w)};
#pragma unroll
            for (int i = 0; i < 8; ++i)
#pragma unroll
                for (int j = 0; j < 4; ++j) acc[i][j] = fma2(ra[i], rb[j], acc[i][j]);
        }
        if (nxt) {
            const int nb = buf ^ 1;
            As[nb][lc+0][lr] = pack2(af.x, af.x); As[nb][lc+1][lr] = pack2(af.y, af.y);
            As[nb][lc+2][lr] = pack2(af.z, af.z); As[nb][lc+3][lr] = pack2(af.w, af.w);
            Bs[nb][lc+0][lr] = bf.x; Bs[nb][lc+1][lr] = bf.y;
            Bs[nb][lc+2][lr] = bf.z; Bs[nb][lc+3][lr] = bf.w;
        }
        __syncthreads();
        buf ^= 1;
    }

    const float4* bias4 = reinterpret_cast<const float4*>(bias + bn + (tx << 3));
    float4 bv0 = bias4[0], bv1 = bias4[1];
    float bb[8] = {bv0.x, bv0.y, bv0.z, bv0.w, bv1.x, bv1.y, bv1.z, bv1.w};
#pragma unroll
    for (int i = 0; i < 8; ++i) {
        int cm = bm + (ty << 3) + i;
        if (cm < M) {
            float o[8];
#pragma unroll
            for (int j = 0; j < 4; ++j) unpack2(acc[i][j], o[2*j], o[2*j+1]);
#pragma unroll
            for (int j = 0; j < 8; ++j) {
                float v = o[j] + bb[j];
                if (SIG) v = 1.0f / (1.0f + __expf(-v));
                o[j] = v;
            }
            float4* cp = reinterpret_cast<float4*>(C + (size_t)cm * ldc + bn + (tx << 3));
            cp[0] = make_float4(o[0], o[1], o[2], o[3]);
            cp[1] = make_float4(o[4], o[5], o[6], o[7]);
        }
    }
}

// Persistent recurrence v3b: 128 CTAs x 512 thr, one row per warp,
// tag-carrying u64 sync words (L2-resident), 4 words polled per thread
// (512*4 = 2048 = full h vector), two barriers per step,
// g_pre register-prefetched one step ahead.
__global__ void __launch_bounds__(512, 1)
rnn_kernel(const float* __restrict__ Wh) {
    const int tid = threadIdx.x;
    const int warp = tid >> 5, lane = tid & 31;
    const int row = (blockIdx.x << 4) + warp;

    // weights for this warp's row: cols j*128 + lane*4 (+0..3), j=0..15
    ull wreg[32];
    {
        const float* wp = Wh + (size_t)row * (2 * DH) + DH + (lane << 2);
#pragma unroll
        for (int j = 0; j < 16; ++j) {
            float4 v = *reinterpret_cast<const float4*>(wp + (j << 7));
            wreg[2*j]   = pack2(v.x, v.y);
            wreg[2*j+1] = pack2(v.z, v.w);
        }
    }

    __shared__ __align__(16) float hs[DH];

    float prev = 0.f;
    if (lane == 0) prev = g_pre[(size_t)1 * DH + row];

    for (int t = 1; t < T_STEPS; ++t) {
        // ---- phase A: poll my 4 sync words of h_{t-1} (pure L2) ----
        const ull* sp = &g_sync[(t - 1) & 1][tid << 2];
        const ull want = (ull)(t - 1);
        ull v0, v1, v2, v3;
        do {
            ld_rlx_2u64(sp + 0, v0, v1);
            ld_rlx_2u64(sp + 2, v2, v3);
        } while ((v0 >> 32) != want || (v1 >> 32) != want ||
                 (v2 >> 32) != want || (v3 >> 32) != want);
        *reinterpret_cast<float4*>(&hs[tid << 2]) = make_float4(
            __uint_as_float((unsigned)v0), __uint_as_float((unsigned)v1),
            __uint_as_float((unsigned)v2), __uint_as_float((unsigned)v3));
        __syncthreads();

        // ---- phase B: dot(row, h) + reduce + publish ----
        ull acc0 = 0ULL, acc1 = 0ULL;
#pragma unroll
        for (int j = 0; j < 16; ++j) {
            float4 hv = *reinterpret_cast<const float4*>(&hs[(j << 7) + (lane << 2)]);
            acc0 = fma2(wreg[2*j],   pack2(hv.x, hv.y), acc0);
            acc1 = fma2(wreg[2*j+1], pack2(hv.z, hv.w), acc1);
        }
        float a, b, c, d;
        unpack2(acc0, a, b); unpack2(acc1, c, d);
        float s = (a + b) + (c + d);
#pragma unroll
        for (int o = 16; o > 0; o >>= 1) s += __shfl_xor_sync(0xffffffffu, s, o);
        if (lane == 0) {
            float h = 1.0f / (1.0f + __expf(-(s + prev)));
            st_rlx_u64(&g_sync[t & 1][row],
                       ((ull)(unsigned)t << 32) | (ull)__float_as_uint(h));
            g_H[(size_t)t * DH + row] = h;                 // for the out-GEMM
            if (t + 1 < T_STEPS)                           // prefetch next pre
                prev = g_pre[(size_t)(t + 1) * DH + row];
        }
        __syncthreads();  // keep next step's poll behind this CTA's publish
    }
}

extern "C" void kernel_launch(void* const* d_in, const int* in_sizes, int n_in,
                              void* d_out, int out_size) {
    (void)in_sizes; (void)n_in; (void)out_size;
    const float* features = (const float*)d_in[0];
    const float* caption  = (const float*)d_in[1];
    const float* W_h      = (const float*)d_in[2];
    const float* b_h      = (const float*)d_in[3];
    const float* W_o      = (const float*)d_in[4];
    const float* b_o      = (const float*)d_in[5];
    float* out = (float*)d_out;

    void *preV = nullptr, *hV = nullptr;
    cudaGetSymbolAddress(&preV, g_pre);
    cudaGetSymbolAddress(&hV, g_H);
    float* pre = (float*)preV;
    float* H   = (float*)hV;

    init_kernel<<<8, 256>>>(features, caption, out);

    dim3 grid(DH / 128, (T_STEPS - 1 + 127) / 128);  // 16 x 64
    sgemm_nt<0><<<grid, 256>>>(caption, DH, W_h, 2 * DH, b_h,
                               pre + DH, DH, T_STEPS - 1, DH);
    rnn_kernel<<<RNN_CTAS, 512>>>(W_h);
    sgemm_nt<1><<<grid, 256>>>(H + DH, DH, W_o, DH, b_o,
                               out + DH, DH, T_STEPS - 1, DH);
}

// round 8
// speedup vs baseline: 1.5415x; 1.0134x over previous
#include <cuda_runtime.h>

#define T_STEPS 8192
#define DH 2048
#define RNN_CTAS 128
#define SENT 0xFFC00001u

typedef unsigned long long ull;

__device__ __align__(16) float g_pre[(size_t)T_STEPS * DH];
__device__ __align__(16) float g_H[(size_t)T_STEPS * DH];

__device__ __forceinline__ ull pack2(float a, float b) {
    ull r; asm("mov.b64 %0, {%1, %2};" : "=l"(r) : "f"(a), "f"(b)); return r;
}
__device__ __forceinline__ void unpack2(ull v, float& a, float& b) {
    asm("mov.b64 {%0, %1}, %2;" : "=f"(a), "=f"(b) : "l"(v));
}
__device__ __forceinline__ ull fma2(ull a, ull b, ull c) {
    ull d; asm("fma.rn.f32x2 %0, %1, %2, %3;" : "=l"(d) : "l"(a), "l"(b), "l"(c));
    return d;
}
__device__ __forceinline__ uint4 ld_rlx4(const uint4* p) {
    uint4 v;
    asm volatile("ld.relaxed.gpu.global.v4.u32 {%0,%1,%2,%3}, [%4];"
        : "=r"(v.x), "=r"(v.y), "=r"(v.z), "=r"(v.w) : "l"(p) : "memory");
    return v;
}
__device__ __forceinline__ void st_rlx(float* p, float v) {
    asm volatile("st.relaxed.gpu.global.f32 [%0], %1;" :: "l"(p), "f"(v) : "memory");
}
__device__ __forceinline__ bool has_sent(uint4 v) {
    return (v.x == SENT) | (v.y == SENT) | (v.z == SENT) | (v.w == SENT);
}
__device__ __forceinline__ float sigmoidf_(float x) {
    return 1.0f / (1.0f + __expf(-x));
}

__global__ void init_kernel(const float* __restrict__ features,
                            const float* __restrict__ caption,
                            float* __restrict__ out) {
    int i = blockIdx.x * blockDim.x + threadIdx.x;
    if (i < DH) { g_H[i] = features[i]; out[i] = caption[i]; }
}

// poison H rows 1..T-1 with the sentinel
__global__ void poison_kernel() {
    uint4 s = make_uint4(SENT, SENT, SENT, SENT);
    uint4* p = reinterpret_cast<uint4*>(g_H + DH);
    const size_t n = (size_t)(T_STEPS - 1) * DH / 4;
    const size_t stride = (size_t)gridDim.x * blockDim.x;
    for (size_t k = (size_t)blockIdx.x * blockDim.x + threadIdx.x; k < n; k += stride)
        p[k] = s;
}

// C[m,n] = sum_k A[m*lda+k]*B[n*ldb+k] + bias[n]  (pre-activation GEMM)
__global__ void __launch_bounds__(256, 2)
sgemm_nt(const float* __restrict__ A, int lda,
         const float* __restrict__ B, int ldb,
         const float* __restrict__ bias,
         float* __restrict__ C, int ldc, int M, int K) {
    __shared__ __align__(16) ull   As[2][8][128];
    __shared__ __align__(16) float Bs[2][8][128];
    const int tid = threadIdx.x;
    const int tx = tid & 15, ty = tid >> 4;
    const int bm = blockIdx.y << 7, bn = blockIdx.x << 7;
    const int lr = tid >> 1, lc = (tid & 1) << 2;
    const float* Ap = A + (size_t)(bm + lr) * lda + lc;
    const float* Bp = B + (size_t)(bn + lr) * ldb + lc;
    const bool av = (bm + lr) < M;

    ull acc[8][4];
#pragma unroll
    for (int i = 0; i < 8; ++i)
#pragma unroll
        for (int j = 0; j < 4; ++j) acc[i][j] = 0ULL;

    float4 af = av ? *reinterpret_cast<const float4*>(Ap) : make_float4(0,0,0,0);
    float4 bf = *reinterpret_cast<const float4*>(Bp);
    As[0][lc+0][lr] = pack2(af.x, af.x); As[0][lc+1][lr] = pack2(af.y, af.y);
    As[0][lc+2][lr] = pack2(af.z, af.z); As[0][lc+3][lr] = pack2(af.w, af.w);
    Bs[0][lc+0][lr] = bf.x; Bs[0][lc+1][lr] = bf.y;
    Bs[0][lc+2][lr] = bf.z; Bs[0][lc+3][lr] = bf.w;
    __syncthreads();

    const int nIter = K >> 3;
    int buf = 0;
    for (int kt = 0; kt < nIter; ++kt) {
        const bool nxt = (kt + 1) < nIter;
        if (nxt) {
            af = av ? *reinterpret_cast<const float4*>(Ap + ((kt+1) << 3)) : make_float4(0,0,0,0);
            bf = *reinterpret_cast<const float4*>(Bp + ((kt+1) << 3));
        }
#pragma unroll
        for (int k = 0; k < 8; ++k) {
            const ulonglong2* ap2 = reinterpret_cast<const ulonglong2*>(&As[buf][k][ty << 3]);
            ulonglong2 a01 = ap2[0], a23 = ap2[1], a45 = ap2[2], a67 = ap2[3];
            const float4* bp4 = reinterpret_cast<const float4*>(&Bs[buf][k][tx << 3]);
            float4 b0 = bp4[0], b1 = bp4[1];
            ull ra[8] = {a01.x, a01.y, a23.x, a23.y, a45.x, a45.y, a67.x, a67.y};
            ull rb[4] = {pack2(b0.x, b0.y), pack2(b0.z, b0.w),
                         pack2(b1.x, b1.y), pack2(b1.z, b1.w)};
#pragma unroll
            for (int i = 0; i < 8; ++i)
#pragma unroll
                for (int j = 0; j < 4; ++j) acc[i][j] = fma2(ra[i], rb[j], acc[i][j]);
        }
        if (nxt) {
            const int nb = buf ^ 1;
            As[nb][lc+0][lr] = pack2(af.x, af.x); As[nb][lc+1][lr] = pack2(af.y, af.y);
            As[nb][lc+2][lr] = pack2(af.z, af.z); As[nb][lc+3][lr] = pack2(af.w, af.w);
            Bs[nb][lc+0][lr] = bf.x; Bs[nb][lc+1][lr] = bf.y;
            Bs[nb][lc+2][lr] = bf.z; Bs[nb][lc+3][lr] = bf.w;
        }
        __syncthreads();
        buf ^= 1;
    }

    const float4* bias4 = reinterpret_cast<const float4*>(bias + bn + (tx << 3));
    float4 bv0 = bias4[0], bv1 = bias4[1];
    float bb[8] = {bv0.x, bv0.y, bv0.z, bv0.w, bv1.x, bv1.y, bv1.z, bv1.w};
#pragma unroll
    for (int i = 0; i < 8; ++i) {
        int cm = bm + (ty << 3) + i;
        if (cm < M) {
            float o[8];
#pragma unroll
            for (int j = 0; j < 4; ++j) unpack2(acc[i][j], o[2*j], o[2*j+1]);
#pragma unroll
            for (int j = 0; j < 8; ++j) o[j] += bb[j];
            float4* cp = reinterpret_cast<float4*>(C + (size_t)cm * ldc + bn + (tx << 3));
            cp[0] = make_float4(o[0], o[1], o[2], o[3]);
            cp[1] = make_float4(o[4], o[5], o[6], o[7]);
        }
    }
}

// Persistent recurrence (R3 structure, 18.8ms) + FUSED output projection:
// after publishing h_t, each warp computes one row of y_{t-1} = sig(W_o h_{t-1}
// + b_o) from the h staged this iteration, using a 128KB W_o slice in SMEM.
// This fills the dead poll window and deletes the output GEMM entirely.
__global__ void __launch_bounds__(512, 1)
rnn_kernel(const float* __restrict__ Wh, const float* __restrict__ Wo,
           const float* __restrict__ bo, float* __restrict__ out) {
    const int tid = threadIdx.x;
    const int warp = tid >> 5, lane = tid & 31;
    const int rg = warp >> 2, chunk = warp & 3;
    const int rowBase = blockIdx.x << 4;
    const int colBase = (chunk << 9) + (lane << 4);

    extern __shared__ __align__(16) float smem[];
    float* Wo_s = smem;                    // 16 x 2048
    float* hs   = smem + 16 * DH;          // 2 x 2048 (parity)
    float* part = hs + 2 * DH;             // 2048
    float* preS = part + DH;               // 2 x 16

    // W_hh slice -> registers (R3 layout: 4 rows x 512 cols per warp)
    ull w01[16], w23[16];
    {
        const float* p0 = Wh + (size_t)(rowBase + (rg << 2)) * (2 * DH) + DH + colBase;
#pragma unroll
        for (int q = 0; q < 4; ++q) {
            float4 v0 = reinterpret_cast<const float4*>(p0         )[q];
            float4 v1 = reinterpret_cast<const float4*>(p0 + 2 * DH)[q];
            float4 v2 = reinterpret_cast<const float4*>(p0 + 4 * DH)[q];
            float4 v3 = reinterpret_cast<const float4*>(p0 + 6 * DH)[q];
            w01[q*4+0] = pack2(v0.x, v1.x); w01[q*4+1] = pack2(v0.y, v1.y);
            w01[q*4+2] = pack2(v0.z, v1.z); w01[q*4+3] = pack2(v0.w, v1.w);
            w23[q*4+0] = pack2(v2.x, v3.x); w23[q*4+1] = pack2(v2.y, v3.y);
            w23[q*4+2] = pack2(v2.z, v3.z); w23[q*4+3] = pack2(v2.w, v3.w);
        }
    }
    // W_o slice (16 rows, 128KB) -> SMEM
    {
        const float4* src = reinterpret_cast<const float4*>(Wo + (size_t)rowBase * DH);
        float4* dst = reinterpret_cast<float4*>(Wo_s);
        for (int i = tid; i < 16 * DH / 4; i += 512) dst[i] = src[i];
    }
    const float myBo = bo[rowBase + warp];

    for (int t = 1; t < T_STEPS; ++t) {
        const int pb = t & 1;
        float* hcur = hs + pb * DH;

        if (warp < 4) {
            // poll 64B of h_{t-1}: 4x v4 relaxed loads, re-issue until clean
            const uint4* hp = reinterpret_cast<const uint4*>(
                &g_H[(size_t)(t - 1) * DH]) + (tid << 2);
            uint4 a, b, c, d;
            for (;;) {
                a = ld_rlx4(hp + 0); b = ld_rlx4(hp + 1);
                c = ld_rlx4(hp + 2); d = ld_rlx4(hp + 3);
                if (!(has_sent(a) | has_sent(b) | has_sent(c) | has_sent(d))) break;
            }
            uint4* o = reinterpret_cast<uint4*>(&hcur[tid << 4]);
            o[0] = a; o[1] = b; o[2] = c; o[3] = d;
        } else if (warp == 4 && lane < 16) {
            preS[pb * 16 + lane] = g_pre[(size_t)t * DH + rowBase + lane];
        }
        __syncthreads();

        // recurrence dot: 4 rows x 512 cols per warp, f32x2 packed
        ull acc01 = 0ULL, acc23 = 0ULL;
#pragma unroll
        for (int q = 0; q < 4; ++q) {
            float4 hv = *reinterpret_cast<const float4*>(&hcur[colBase + (q << 2)]);
            ull h0 = pack2(hv.x, hv.x), h1 = pack2(hv.y, hv.y);
            ull h2 = pack2(hv.z, hv.z), h3 = pack2(hv.w, hv.w);
            acc01 = fma2(w01[q*4+0], h0, acc01); acc23 = fma2(w23[q*4+0], h0, acc23);
            acc01 = fma2(w01[q*4+1], h1, acc01); acc23 = fma2(w23[q*4+1], h1, acc23);
            acc01 = fma2(w01[q*4+2], h2, acc01); acc23 = fma2(w23[q*4+2], h2, acc23);
            acc01 = fma2(w01[q*4+3], h3, acc01); acc23 = fma2(w23[q*4+3], h3, acc23);
        }
        float a0, a1, a2, a3;
        unpack2(acc01, a0, a1); unpack2(acc23, a2, a3);
        const int rb4 = rg << 2, off = (chunk << 5) + lane;
        part[(rb4+0)*128 + off] = a0;
        part[(rb4+1)*128 + off] = a1;
        part[(rb4+2)*128 + off] = a2;
        part[(rb4+3)*128 + off] = a3;
        __syncthreads();

        float s = part[warp*128 + lane] + part[warp*128 + 32 + lane] +
                  part[warp*128 + 64 + lane] + part[warp*128 + 96 + lane];
#pragma unroll
        for (int o = 16; o > 0; o >>= 1) s += __shfl_xor_sync(0xffffffffu, s, o);
        if (lane == 0) {
            float x = s + preS[pb * 16 + warp];
            st_rlx(&g_H[(size_t)t * DH + rowBase + warp], sigmoidf_(x));
        }

        // fused output row: y_{t-1}[rowBase+warp] from h_{t-1} (= hcur).
        // Off the serial chain; fills the poll window. hcur is parity-safe.
        if (t >= 2) {
            const float* wrow = Wo_s + warp * DH;
            ull ya = 0ULL, yb = 0ULL;
#pragma unroll
            for (int j = 0; j < 16; ++j) {
                const int c = (j << 7) + (lane << 2);
                float4 wv = *reinterpret_cast<const float4*>(wrow + c);
                float4 hv = *reinterpret_cast<const float4*>(hcur + c);
                ya = fma2(pack2(wv.x, wv.y), pack2(hv.x, hv.y), ya);
                yb = fma2(pack2(wv.z, wv.w), pack2(hv.z, hv.w), yb);
            }
            float p, q, r, w2;
            unpack2(ya, p, q); unpack2(yb, r, w2);
            float ys = (p + q) + (r + w2);
#pragma unroll
            for (int o = 16; o > 0; o >>= 1) ys += __shfl_xor_sync(0xffffffffu, ys, o);
            if (lane == 0)
                out[(size_t)(t - 1) * DH + rowBase + warp] = sigmoidf_(ys + myBo);
        }
    }

    // epilogue: y_{T-1} needs the full h_{T-1} -> one more poll + dot
    {
        float* hcur = hs;  // parity 0 buffer is free (last loop iter used pb=1)
        if (warp < 4) {
            const uint4* hp = reinterpret_cast<const uint4*>(
                &g_H[(size_t)(T_STEPS - 1) * DH]) + (tid << 2);
            uint4 a, b, c, d;
            for (;;) {
                a = ld_rlx4(hp + 0); b = ld_rlx4(hp + 1);
                c = ld_rlx4(hp + 2); d = ld_rlx4(hp + 3);
                if (!(has_sent(a) | has_sent(b) | has_sent(c) | has_sent(d))) break;
            }
            uint4* o = reinterpret_cast<uint4*>(&hcur[tid << 4]);
            o[0] = a; o[1] = b; o[2] = c; o[3] = d;
        }
        __syncthreads();
        const float* wrow = Wo_s + warp * DH;
        ull ya = 0ULL, yb = 0ULL;
#pragma unroll
        for (int j = 0; j < 16; ++j) {
            const int c = (j << 7) + (lane << 2);
            float4 wv = *reinterpret_cast<const float4*>(wrow + c);
            float4 hv = *reinterpret_cast<const float4*>(hcur + c);
            ya = fma2(pack2(wv.x, wv.y), pack2(hv.x, hv.y), ya);
            yb = fma2(pack2(wv.z, wv.w), pack2(hv.z, hv.w), yb);
        }
        float p, q, r, w2;
        unpack2(ya, p, q); unpack2(yb, r, w2);
        float ys = (p + q) + (r + w2);
#pragma unroll
        for (int o = 16; o > 0; o >>= 1) ys += __shfl_xor_sync(0xffffffffu, ys, o);
        if (lane == 0)
            out[(size_t)(T_STEPS - 1) * DH + rowBase + warp] = sigmoidf_(ys + myBo);
    }
}

#define RNN_SMEM ((16 * DH + 2 * DH + DH + 32) * 4)

extern "C" void kernel_launch(void* const* d_in, const int* in_sizes, int n_in,
                              void* d_out, int out_size) {
    (void)in_sizes; (void)n_in; (void)out_size;
    const float* features = (const float*)d_in[0];
    const float* caption  = (const float*)d_in[1];
    const float* W_h      = (const float*)d_in[2];
    const float* b_h      = (const float*)d_in[3];
    const float* W_o      = (const float*)d_in[4];
    const float* b_o      = (const float*)d_in[5];
    float* out = (float*)d_out;

    void *preV = nullptr;
    cudaGetSymbolAddress(&preV, g_pre);
    float* pre = (float*)preV;

    cudaFuncSetAttribute(rnn_kernel,
                         cudaFuncAttributeMaxDynamicSharedMemorySize, RNN_SMEM);

    init_kernel<<<8, 256>>>(features, caption, out);
    poison_kernel<<<1024, 256>>>();

    dim3 grid(DH / 128, (T_STEPS - 1 + 127) / 128);  // 16 x 64
    sgemm_nt<<<grid, 256>>>(caption, DH, W_h, 2 * DH, b_h,
                            pre + DH, DH, T_STEPS - 1, DH);
    rnn_kernel<<<RNN_CTAS, 512, RNN_SMEM>>>(W_h, W_o, b_o, out);
}

// round 9
// speedup vs baseline: 1.6162x; 1.0485x over previous
#include <cuda_runtime.h>

#define T_STEPS 8192
#define DH 2048
#define RNN_CTAS 128
#define SENT 0xFFC00001u

typedef unsigned long long ull;

__device__ __align__(16) float g_pre[(size_t)T_STEPS * DH];
__device__ __align__(16) float g_H[(size_t)T_STEPS * DH];

__device__ __forceinline__ ull pack2(float a, float b) {
    ull r; asm("mov.b64 %0, {%1, %2};" : "=l"(r) : "f"(a), "f"(b)); return r;
}
__device__ __forceinline__ void unpack2(ull v, float& a, float& b) {
    asm("mov.b64 {%0, %1}, %2;" : "=f"(a), "=f"(b) : "l"(v));
}
__device__ __forceinline__ ull fma2(ull a, ull b, ull c) {
    ull d; asm("fma.rn.f32x2 %0, %1, %2, %3;" : "=l"(d) : "l"(a), "l"(b), "l"(c));
    return d;
}
__device__ __forceinline__ uint4 ld_rlx4(const uint4* p) {
    uint4 v;
    asm volatile("ld.relaxed.gpu.global.v4.u32 {%0,%1,%2,%3}, [%4];"
        : "=r"(v.x), "=r"(v.y), "=r"(v.z), "=r"(v.w) : "l"(p) : "memory");
    return v;
}
__device__ __forceinline__ void st_rlx(float* p, float v) {
    asm volatile("st.relaxed.gpu.global.f32 [%0], %1;" :: "l"(p), "f"(v) : "memory");
}
__device__ __forceinline__ bool has_sent(uint4 v) {
    return (v.x == SENT) | (v.y == SENT) | (v.z == SENT) | (v.w == SENT);
}
__device__ __forceinline__ float sigmoidf_(float x) {
    return 1.0f / (1.0f + __expf(-x));
}

__global__ void init_kernel(const float* __restrict__ features,
                            const float* __restrict__ caption,
                            float* __restrict__ out) {
    int i = blockIdx.x * blockDim.x + threadIdx.x;
    if (i < DH) { g_H[i] = features[i]; out[i] = caption[i]; }
}

// poison H rows 1..T-1 with the sentinel
__global__ void poison_kernel() {
    uint4 s = make_uint4(SENT, SENT, SENT, SENT);
    uint4* p = reinterpret_cast<uint4*>(g_H + DH);
    const size_t n = (size_t)(T_STEPS - 1) * DH / 4;
    const size_t stride = (size_t)gridDim.x * blockDim.x;
    for (size_t k = (size_t)blockIdx.x * blockDim.x + threadIdx.x; k < n; k += stride)
        p[k] = s;
}

// C[m,n] = sum_k A[m*lda+k]*B[n*ldb+k] + bias[n], optional sigmoid.
template <int SIG>
__global__ void __launch_bounds__(256, 2)
sgemm_nt(const float* __restrict__ A, int lda,
         const float* __restrict__ B, int ldb,
         const float* __restrict__ bias,
         float* __restrict__ C, int ldc, int M, int K) {
    __shared__ __align__(16) ull   As[2][8][128];
    __shared__ __align__(16) float Bs[2][8][128];
    const int tid = threadIdx.x;
    const int tx = tid & 15, ty = tid >> 4;
    const int bm = blockIdx.y << 7, bn = blockIdx.x << 7;
    const int lr = tid >> 1, lc = (tid & 1) << 2;
    const float* Ap = A + (size_t)(bm + lr) * lda + lc;
    const float* Bp = B + (size_t)(bn + lr) * ldb + lc;
    const bool av = (bm + lr) < M;

    ull acc[8][4];
#pragma unroll
    for (int i = 0; i < 8; ++i)
#pragma unroll
        for (int j = 0; j < 4; ++j) acc[i][j] = 0ULL;

    float4 af = av ? *reinterpret_cast<const float4*>(Ap) : make_float4(0,0,0,0);
    float4 bf = *reinterpret_cast<const float4*>(Bp);
    As[0][lc+0][lr] = pack2(af.x, af.x); As[0][lc+1][lr] = pack2(af.y, af.y);
    As[0][lc+2][lr] = pack2(af.z, af.z); As[0][lc+3][lr] = pack2(af.w, af.w);
    Bs[0][lc+0][lr] = bf.x; Bs[0][lc+1][lr] = bf.y;
    Bs[0][lc+2][lr] = bf.z; Bs[0][lc+3][lr] = bf.w;
    __syncthreads();

    const int nIter = K >> 3;
    int buf = 0;
    for (int kt = 0; kt < nIter; ++kt) {
        const bool nxt = (kt + 1) < nIter;
        if (nxt) {
            af = av ? *reinterpret_cast<const float4*>(Ap + ((kt+1) << 3)) : make_float4(0,0,0,0);
            bf = *reinterpret_cast<const float4*>(Bp + ((kt+1) << 3));
        }
#pragma unroll
        for (int k = 0; k < 8; ++k) {
            const ulonglong2* ap2 = reinterpret_cast<const ulonglong2*>(&As[buf][k][ty << 3]);
            ulonglong2 a01 = ap2[0], a23 = ap2[1], a45 = ap2[2], a67 = ap2[3];
            const float4* bp4 = reinterpret_cast<const float4*>(&Bs[buf][k][tx << 3]);
            float4 b0 = bp4[0], b1 = bp4[1];
            ull ra[8] = {a01.x, a01.y, a23.x, a23.y, a45.x, a45.y, a67.x, a67.y};
            ull rb[4] = {pack2(b0.x, b0.y), pack2(b0.z, b0.w),
                         pack2(b1.x, b1.y), pack2(b1.z, b1.w)};
#pragma unroll
            for (int i = 0; i < 8; ++i)
#pragma unroll
                for (int j = 0; j < 4; ++j) acc[i][j] = fma2(ra[i], rb[j], acc[i][j]);
        }
        if (nxt) {
            const int nb = buf ^ 1;
            As[nb][lc+0][lr] = pack2(af.x, af.x); As[nb][lc+1][lr] = pack2(af.y, af.y);
            As[nb][lc+2][lr] = pack2(af.z, af.z); As[nb][lc+3][lr] = pack2(af.w, af.w);
            Bs[nb][lc+0][lr] = bf.x; Bs[nb][lc+1][lr] = bf.y;
            Bs[nb][lc+2][lr] = bf.z; Bs[nb][lc+3][lr] = bf.w;
        }
        __syncthreads();
        buf ^= 1;
    }

    const float4* bias4 = reinterpret_cast<const float4*>(bias + bn + (tx << 3));
    float4 bv0 = bias4[0], bv1 = bias4[1];
    float bb[8] = {bv0.x, bv0.y, bv0.z, bv0.w, bv1.x, bv1.y, bv1.z, bv1.w};
#pragma unroll
    for (int i = 0; i < 8; ++i) {
        int cm = bm + (ty << 3) + i;
        if (cm < M) {
            float o[8];
#pragma unroll
            for (int j = 0; j < 4; ++j) unpack2(acc[i][j], o[2*j], o[2*j+1]);
#pragma unroll
            for (int j = 0; j < 8; ++j) {
                float v = o[j] + bb[j];
                if (SIG) v = 1.0f / (1.0f + __expf(-v));
                o[j] = v;
            }
            float4* cp = reinterpret_cast<float4*>(C + (size_t)cm * ldc + bn + (tx << 3));
            cp[0] = make_float4(o[0], o[1], o[2], o[3]);
            cp[1] = make_float4(o[4], o[5], o[6], o[7]);
        }
    }
}

// Persistent recurrence v4: pipelined poll->compute.
// CTA owns 16 rows. Warp w owns col slice [w*128, w*128+128) of ALL 16 rows;
// lane owns 4 cols. Lane polls exactly its 4 h-values (one uint4) and FMAs
// them immediately — no staging, no pre-compute barrier. One barrier/step;
// part[] parity-buffered. Warp w then reduces row w (512 partials).
__global__ void __launch_bounds__(512, 1)
rnn_kernel(const float* __restrict__ Wh) {
    const int tid = threadIdx.x;
    const int warp = tid >> 5, lane = tid & 31;
    const int rowBase = blockIdx.x << 4;
    const int col0 = (warp << 7) + (lane << 2);   // this lane's 4 columns

    // weights: rows rowBase+0..15 at my 4 cols, packed in row pairs.
    // wp[r2][j] = (W[2r2][col0+j], W[2r2+1][col0+j])
    ull wp[8][4];
#pragma unroll
    for (int r2 = 0; r2 < 8; ++r2) {
        const float* pa = Wh + (size_t)(rowBase + 2*r2)     * (2*DH) + DH + col0;
        const float* pb = Wh + (size_t)(rowBase + 2*r2 + 1) * (2*DH) + DH + col0;
        float4 va = *reinterpret_cast<const float4*>(pa);
        float4 vb = *reinterpret_cast<const float4*>(pb);
        wp[r2][0] = pack2(va.x, vb.x); wp[r2][1] = pack2(va.y, vb.y);
        wp[r2][2] = pack2(va.z, vb.z); wp[r2][3] = pack2(va.w, vb.w);
    }

    extern __shared__ __align__(16) float part[];   // [2][16][512]

    const int myRow = rowBase + warp;               // row this warp reduces
    float prev = (lane == 0) ? g_pre[(size_t)1 * DH + myRow] : 0.f;

    for (int t = 1; t < T_STEPS; ++t) {
        const int pb = t & 1;

        // ---- poll my own 4 h-values (the same ones my FMAs consume) ----
        const uint4* hp = reinterpret_cast<const uint4*>(
            &g_H[(size_t)(t - 1) * DH + col0]);
        uint4 v;
        do { v = ld_rlx4(hp); } while (has_sent(v));
        const float h0 = __uint_as_float(v.x), h1 = __uint_as_float(v.y);
        const float h2 = __uint_as_float(v.z), h3 = __uint_as_float(v.w);
        const ull hh0 = pack2(h0, h0), hh1 = pack2(h1, h1);
        const ull hh2 = pack2(h2, h2), hh3 = pack2(h3, h3);

        // ---- 16 rows x 4 cols of MACs, 8 independent f32x2 chains ----
        float* pp = part + pb * (16 * 512) + (warp << 5) + lane;
#pragma unroll
        for (int r2 = 0; r2 < 8; ++r2) {
            ull acc = fma2(wp[r2][0], hh0, 0ULL);
            acc = fma2(wp[r2][1], hh1, acc);
            acc = fma2(wp[r2][2], hh2, acc);
            acc = fma2(wp[r2][3], hh3, acc);
            float pa, pbf;
            unpack2(acc, pa, pbf);
            pp[(2*r2)     << 9] = pa;      // part[pb][2r2][warp*32+lane]
            pp[(2*r2 + 1) << 9] = pbf;
        }
        __syncthreads();   // sole barrier per step

        // ---- warp w reduces row w: 512 partials ----
        const float* rp = part + pb * (16 * 512) + (warp << 9);
        float4 s0 = reinterpret_cast<const float4*>(rp)[lane];
        float4 s1 = reinterpret_cast<const float4*>(rp)[lane + 32];
        float4 s2 = reinterpret_cast<const float4*>(rp)[lane + 64];
        float4 s3 = reinterpret_cast<const float4*>(rp)[lane + 96];
        float s = ((s0.x + s0.y) + (s0.z + s0.w)) + ((s1.x + s1.y) + (s1.z + s1.w))
                + ((s2.x + s2.y) + (s2.z + s2.w)) + ((s3.x + s3.y) + (s3.z + s3.w));
#pragma unroll
        for (int o = 16; o > 0; o >>= 1) s += __shfl_xor_sync(0xffffffffu, s, o);
        if (lane == 0) {
            st_rlx(&g_H[(size_t)t * DH + myRow], sigmoidf_(s + prev));
            if (t + 1 < T_STEPS) prev = g_pre[(size_t)(t + 1) * DH + myRow];
        }
        // no trailing barrier: part is parity-buffered; a warp can only
        // write part[pb] again (t+2) after the t+1 barrier, which releases
        // only after every warp's step-t reduce has completed.
    }
}

#define RNN_SMEM (2 * 16 * 512 * 4)   // 64KB

extern "C" void kernel_launch(void* const* d_in, const int* in_sizes, int n_in,
                              void* d_out, int out_size) {
    (void)in_sizes; (void)n_in; (void)out_size;
    const float* features = (const float*)d_in[0];
    const float* caption  = (const float*)d_in[1];
    const float* W_h      = (const float*)d_in[2];
    const float* b_h      = (const float*)d_in[3];
    const float* W_o      = (const float*)d_in[4];
    const float* b_o      = (const float*)d_in[5];
    float* out = (float*)d_out;

    void *preV = nullptr, *hV = nullptr;
    cudaGetSymbolAddress(&preV, g_pre);
    cudaGetSymbolAddress(&hV, g_H);
    float* pre = (float*)preV;
    float* H   = (float*)hV;

    cudaFuncSetAttribute(rnn_kernel,
                         cudaFuncAttributeMaxDynamicSharedMemorySize, RNN_SMEM);

    init_kernel<<<8, 256>>>(features, caption, out);
    poison_kernel<<<1024, 256>>>();

    dim3 grid(DH / 128, (T_STEPS - 1 + 127) / 128);  // 16 x 64
    sgemm_nt<0><<<grid, 256>>>(caption, DH, W_h, 2 * DH, b_h,
                               pre + DH, DH, T_STEPS - 1, DH);
    rnn_kernel<<<RNN_CTAS, 512, RNN_SMEM>>>(W_h);
    sgemm_nt<1><<<grid, 256>>>(H + DH, DH, W_o, DH, b_o,
                               out + DH, DH, T_STEPS - 1, DH);
}